// round 13
// baseline (speedup 1.0000x reference)
#include <cuda_runtime.h>
#include <cuda_bf16.h>

#define B_ROWS 8192
#define ITEM_NUM 10000
#define THREADS 512
#define N4 (ITEM_NUM / 4)       /* 2500 float4 */
#define FP_SCALE 4294967296.0   /* 2^32 fixed-point scale */

// Scratch (no cudaMalloc allowed). Winner resets both each launch (replay-safe).
__device__ unsigned long long g_sum = 0ull;
__device__ unsigned int g_arrived = 0u;

__global__ __launch_bounds__(THREADS, 4)
void dq_smemw_kernel(const float* __restrict__ hs,
                     const float* __restrict__ tq,
                     const float* __restrict__ rewards,
                     const float* __restrict__ discount,
                     const unsigned char* __restrict__ is_done,
                     const float* __restrict__ W,
                     const float* __restrict__ bias,
                     float* __restrict__ out) {
    __shared__ float4 s_w[N4];          // 40 KB: W staged once per CTA
    __shared__ float  sq[THREADS / 32];
    __shared__ float  sn[THREADS / 32];

    const int row = blockIdx.x;
    const float4* __restrict__ hsr = reinterpret_cast<const float4*>(hs + (size_t)row * ITEM_NUM);
    const float4* __restrict__ tqr = reinterpret_cast<const float4*>(tq + (size_t)row * ITEM_NUM);
    const float4* __restrict__ w4  = reinterpret_cast<const float4*>(W);

    // Cooperative stage of W into smem (L2-hit after first wave).
    for (int i = threadIdx.x; i < N4; i += THREADS)
        s_w[i] = w4[i];
    __syncthreads();

    float qs = 0.0f, ns = 0.0f;
    for (int i = threadIdx.x; i < N4; i += THREADS) {
        float4 w = s_w[i];          // LDS: off the L1tex path entirely
        float4 h = hsr[i];
        float4 t = tqr[i];
        qs = fmaf(h.x, w.x, qs); qs = fmaf(h.y, w.y, qs);
        qs = fmaf(h.z, w.z, qs); qs = fmaf(h.w, w.w, qs);
        ns = fmaf(t.x, w.x, ns); ns = fmaf(t.y, w.y, ns);
        ns = fmaf(t.z, w.z, ns); ns = fmaf(t.w, w.w, ns);
    }

    // Warp reduce both sums
    #pragma unroll
    for (int off = 16; off > 0; off >>= 1) {
        qs += __shfl_down_sync(0xFFFFFFFFu, qs, off);
        ns += __shfl_down_sync(0xFFFFFFFFu, ns, off);
    }

    const int lane = threadIdx.x & 31;
    const int wid  = threadIdx.x >> 5;
    if (lane == 0) { sq[wid] = qs; sn[wid] = ns; }
    __syncthreads();

    if (threadIdx.x == 0) {
        float q = 0.0f, n = 0.0f;
        #pragma unroll
        for (int w = 0; w < THREADS / 32; w++) { q += sq[w]; n += sn[w]; }
        const float b = bias[0];
        const float qv  = fmaxf(q + b, 0.0f);
        const float nqv = fmaxf(n + b, 0.0f);
        float ps = fabsf(rewards[row] + discount[0] * nqv - qv);
        if (is_done[row]) ps = 0.0f;

        // Deterministic accumulation: fixed-point u64 atomic (associative).
        const unsigned long long q64 = (unsigned long long)((double)ps * FP_SCALE);
        atomicAdd(&g_sum, q64);

        // Release-ordered arrival; winner finalizes.
        unsigned int prev;
        asm volatile("atom.add.release.gpu.u32 %0, [%1], %2;"
                     : "=r"(prev)
                     : "l"(&g_arrived), "r"(1u)
                     : "memory");
        if (prev == (unsigned int)(gridDim.x - 1)) {
            __threadfence();  // acquire: all g_sum contributions visible
            unsigned long long total = atomicAdd(&g_sum, 0ull);  // atomic read
            out[0] = (float)((double)total / FP_SCALE / (double)B_ROWS);
            g_sum = 0ull;       // reset for next graph replay
            __threadfence();
            g_arrived = 0u;
        }
    }
}

extern "C" void kernel_launch(void* const* d_in, const int* in_sizes, int n_in,
                              void* d_out, int out_size) {
    const float*         hs       = (const float*)d_in[0];
    // d_in[1] = actions (unused by reference)
    const float*         rewards  = (const float*)d_in[2];
    const float*         discount = (const float*)d_in[3];
    const float*         tq       = (const float*)d_in[4];
    const unsigned char* is_done  = (const unsigned char*)d_in[5];
    const float*         W        = (const float*)d_in[6];
    const float*         bias     = (const float*)d_in[7];
    float* out = (float*)d_out;

    dq_smemw_kernel<<<B_ROWS, THREADS>>>(hs, tq, rewards, discount, is_done, W, bias, out);
}

// round 14
// speedup vs baseline: 1.1786x; 1.1786x over previous
#include <cuda_runtime.h>
#include <cuda_bf16.h>

#define B_ROWS 8192
#define ITEM_NUM 10000
#define HALF_ITEMS (ITEM_NUM / 2)       /* 5000 */
#define N4H (HALF_ITEMS / 4)            /* 1250 float4 per half-row */
#define THREADS 256
#define GRID (B_ROWS * 2)               /* 2 CTAs per row */
#define FP_SCALE 4294967296.0           /* 2^32 fixed-point scale */

// Scratch (no cudaMalloc allowed). All counters self-reset each launch.
__device__ float2 g_part[B_ROWS * 2];          // (q,n) partial per half
__device__ unsigned int g_rowcnt[B_ROWS];      // per-row arrival (0..2)
__device__ unsigned long long g_sum = 0ull;    // fixed-point total
__device__ unsigned int g_arrived = 0u;        // combiner count (0..8192)

__global__ __launch_bounds__(THREADS)
void dq_half_kernel(const float* __restrict__ hs,
                    const float* __restrict__ tq,
                    const float* __restrict__ rewards,
                    const float* __restrict__ discount,
                    const unsigned char* __restrict__ is_done,
                    const float* __restrict__ W,
                    const float* __restrict__ bias,
                    float* __restrict__ out) {
    const int row  = blockIdx.x >> 1;
    const int half = blockIdx.x & 1;
    const size_t base = (size_t)row * ITEM_NUM + (size_t)half * HALF_ITEMS;
    const float4* __restrict__ hsr = reinterpret_cast<const float4*>(hs + base);
    const float4* __restrict__ tqr = reinterpret_cast<const float4*>(tq + base);
    const float4* __restrict__ w4  = reinterpret_cast<const float4*>(W + (size_t)half * HALF_ITEMS);

    float qs = 0.0f, ns = 0.0f;
    for (int i = threadIdx.x; i < N4H; i += THREADS) {
        float4 w = w4[i];
        float4 h = hsr[i];
        float4 t = tqr[i];
        qs = fmaf(h.x, w.x, qs); qs = fmaf(h.y, w.y, qs);
        qs = fmaf(h.z, w.z, qs); qs = fmaf(h.w, w.w, qs);
        ns = fmaf(t.x, w.x, ns); ns = fmaf(t.y, w.y, ns);
        ns = fmaf(t.z, w.z, ns); ns = fmaf(t.w, w.w, ns);
    }

    // Warp reduce both sums
    #pragma unroll
    for (int off = 16; off > 0; off >>= 1) {
        qs += __shfl_down_sync(0xFFFFFFFFu, qs, off);
        ns += __shfl_down_sync(0xFFFFFFFFu, ns, off);
    }

    __shared__ float sq[THREADS / 32];
    __shared__ float sn[THREADS / 32];
    const int lane = threadIdx.x & 31;
    const int wid  = threadIdx.x >> 5;
    if (lane == 0) { sq[wid] = qs; sn[wid] = ns; }
    __syncthreads();

    if (threadIdx.x == 0) {
        float q = 0.0f, n = 0.0f;
        #pragma unroll
        for (int w = 0; w < THREADS / 32; w++) { q += sq[w]; n += sn[w]; }

        // Publish this half's partial, then release-arrive on the row counter.
        g_part[row * 2 + half] = make_float2(q, n);
        unsigned int prev;
        asm volatile("atom.add.release.gpu.u32 %0, [%1], %2;"
                     : "=r"(prev)
                     : "l"(&g_rowcnt[row]), "r"(1u)
                     : "memory");

        if (prev == 1u) {  // second arriver combines (deterministic: slot0 + slot1)
            __threadfence();  // acquire: peer partial visible
            float2 p0 = __ldcg(&g_part[row * 2 + 0]);
            float2 p1 = __ldcg(&g_part[row * 2 + 1]);
            const float b = bias[0];
            const float qv  = fmaxf((p0.x + p1.x) + b, 0.0f);
            const float nqv = fmaxf((p0.y + p1.y) + b, 0.0f);
            float ps = fabsf(rewards[row] + discount[0] * nqv - qv);
            if (is_done[row]) ps = 0.0f;
            g_rowcnt[row] = 0u;  // reset for next graph replay

            // Deterministic fixed-point accumulation (associative integer add).
            const unsigned long long q64 = (unsigned long long)((double)ps * FP_SCALE);
            atomicAdd(&g_sum, q64);

            unsigned int done;
            asm volatile("atom.add.release.gpu.u32 %0, [%1], %2;"
                         : "=r"(done)
                         : "l"(&g_arrived), "r"(1u)
                         : "memory");
            if (done == (unsigned int)(B_ROWS - 1)) {
                __threadfence();
                unsigned long long total = atomicAdd(&g_sum, 0ull);
                out[0] = (float)((double)total / FP_SCALE / (double)B_ROWS);
                g_sum = 0ull;
                __threadfence();
                g_arrived = 0u;
            }
        }
    }
}

extern "C" void kernel_launch(void* const* d_in, const int* in_sizes, int n_in,
                              void* d_out, int out_size) {
    const float*         hs       = (const float*)d_in[0];
    // d_in[1] = actions (unused by reference)
    const float*         rewards  = (const float*)d_in[2];
    const float*         discount = (const float*)d_in[3];
    const float*         tq       = (const float*)d_in[4];
    const unsigned char* is_done  = (const unsigned char*)d_in[5];
    const float*         W        = (const float*)d_in[6];
    const float*         bias     = (const float*)d_in[7];
    float* out = (float*)d_out;

    dq_half_kernel<<<GRID, THREADS>>>(hs, tq, rewards, discount, is_done, W, bias, out);
}